// round 15
// baseline (speedup 1.0000x reference)
#include <cuda_runtime.h>
#include <cuda_bf16.h>
#include <cuda_fp16.h>
#include <cstdint>

typedef unsigned long long ull;

#define NP 2809          // 53*53 patches
#define NPAD 2816        // 22*128
#define LW 53
#define NM 8192          // memories
#define KD 3072          // 3*32*32
#define XPW 84
#define XPC 7056         // 84*84
#define MARGIN 48.0f
#define F16SLACK 8.0f    // f16 D-storage rounding slack for candidate select

#define BM 128
#define BN 64
#define BK 64              // fp8 elements per K-chunk (64 bytes/row)
#define KSTEPS (KD / BK)   // 48
#define LDTB 80            // smem row stride in BYTES (64 + 16 pad, conflict-free)
#define STAGE_BYTES ((BM + BN) * LDTB)      // 15360
#define NSTAGE 3
#define GEMM_SMEM (NSTAGE * STAGE_BYTES)    // 46080

// ---------------- scratch (device globals; no allocations allowed) ----------
__device__ __align__(16) float g_xp[3 * XPC];
__device__ float g_memsq[NM];
__device__ ull   g_best[NP];                    // approx (pass1) key
__device__ ull   g_bestx[NP];                   // exact (rescore) key
__device__ int   g_row[NP];                     // mapping[nn] per patch
__device__ __align__(16) __half g_Dh[(size_t)NP * NM];     // ~46 MB approx distances (f16)
__device__ __align__(16) uint8_t g_A8[(size_t)NPAD * KD];  // 8.7 MB  e4m3 patches
__device__ __align__(16) uint8_t g_B8[(size_t)NM * KD];    // 25 MB   e4m3 memories
__device__ unsigned int g_maxord;

// ---------------- helpers ---------------------------------------------------
__device__ __forceinline__ unsigned int ford(float f) {
    unsigned int u = __float_as_uint(f);
    return (u & 0x80000000u) ? ~u : (u | 0x80000000u);
}
__device__ __forceinline__ float fordinv(unsigned int o) {
    unsigned int u = (o & 0x80000000u) ? (o ^ 0x80000000u) : ~o;
    return __uint_as_float(u);
}
__device__ __forceinline__ ull mkkey(float d, int m) {
    return ((ull)ford(d) << 32) | (unsigned int)m;
}
__device__ __forceinline__ uint32_t s2u(const void* p) {
    uint32_t a;
    asm("{ .reg .u64 t; cvta.to.shared.u64 t, %1; cvt.u32.u64 %0, t; }" : "=r"(a) : "l"(p));
    return a;
}
__device__ __forceinline__ uint32_t pack4_e4m3(float x0, float x1, float x2, float x3) {
    unsigned short lo, hi;
    asm("cvt.rn.satfinite.e4m3x2.f32 %0, %1, %2;" : "=h"(lo) : "f"(x1), "f"(x0));
    asm("cvt.rn.satfinite.e4m3x2.f32 %0, %1, %2;" : "=h"(hi) : "f"(x3), "f"(x2));
    return ((uint32_t)hi << 16) | (uint32_t)lo;
}
__device__ __forceinline__ void ldsm4(uint32_t* r, uint32_t addr) {
    asm volatile("ldmatrix.sync.aligned.m8n8.x4.shared.b16 {%0,%1,%2,%3}, [%4];"
                 : "=r"(r[0]), "=r"(r[1]), "=r"(r[2]), "=r"(r[3]) : "r"(addr));
}
// fp8 MMA with packed f16 accumulators: d/c = 2 b32 regs (4 halves)
__device__ __forceinline__ void mma16832h(uint32_t* d, const uint32_t* a, const uint32_t* b) {
    asm volatile("mma.sync.aligned.m16n8k32.row.col.f16.e4m3.e4m3.f16 "
                 "{%0,%1}, {%2,%3,%4,%5}, {%6,%7}, {%0,%1};"
                 : "+r"(d[0]), "+r"(d[1])
                 : "r"(a[0]), "r"(a[1]), "r"(a[2]), "r"(a[3]), "r"(b[0]), "r"(b[1]));
}
__device__ __forceinline__ void cpasync16(uint32_t dst, const void* src) {
    asm volatile("cp.async.cg.shared.global [%0], [%1], 16;" :: "r"(dst), "l"(src));
}

// ---------------- kernel 1: build padded image + init -----------------------
__global__ void k_init(const float* __restrict__ img) {
    int idx = blockIdx.x * blockDim.x + threadIdx.x;
    if (idx < 3 * XPC) {
        int c = idx / XPC, rem = idx - c * XPC;
        int r = rem / XPW, col = rem - r * XPW;
        int h = r - 10, w = col - 10;
        float v = 0.f;
        if ((unsigned)h < 64u && (unsigned)w < 64u) v = img[(h * 64 + w) * 3 + c];
        g_xp[idx] = v;
    }
    if (idx < NP) g_best[idx] = ~0ull;
    if (idx == 0) g_maxord = 0u;
}

// ---------------- kernel 2: build e4m3 A matrix (patches) -------------------
__global__ void k_buildA() {
    int e = blockIdx.x * blockDim.x + threadIdx.x;   // NPAD * (KD/16)
    if (e >= NPAD * (KD / 16)) return;
    int m = e / (KD / 16), r = e - m * (KD / 16);
    int k = r * 16;
    uint32_t w0 = 0, w1 = 0, w2 = 0, w3 = 0;
    if (m < NP) {
        int i = m / LW, j = m - i * LW;
        int c = k >> 10, rem = k & 1023, kh = rem >> 5, kw = rem & 31;
        const float* src = &g_xp[c * XPC + (i + kh) * XPW + j + kw];
        w0 = pack4_e4m3(src[0],  src[1],  src[2],  src[3]);
        w1 = pack4_e4m3(src[4],  src[5],  src[6],  src[7]);
        w2 = pack4_e4m3(src[8],  src[9],  src[10], src[11]);
        w3 = pack4_e4m3(src[12], src[13], src[14], src[15]);
    }
    *(uint4*)&g_A8[(size_t)m * KD + k] = make_uint4(w0, w1, w2, w3);
}

// ---------------- kernel 3: convert mem to e4m3 + fused row squared norms ---
__global__ void __launch_bounds__(256) k_bconv(const float* __restrict__ mem) {
    __shared__ float red[8];
    int row = blockIdx.x, tid = threadIdx.x;
    const float4* src = (const float4*)(mem + (size_t)row * KD);
    float s = 0.f;
#pragma unroll
    for (int t = 0; t < 3; ++t) {                 // 3*256*4 = 3072
        int e = tid + t * 256;
        float4 v = src[e];
        *(uint32_t*)&g_B8[(size_t)row * KD + e * 4] = pack4_e4m3(v.x, v.y, v.z, v.w);
        s += v.x * v.x + v.y * v.y + v.z * v.z + v.w * v.w;
    }
#pragma unroll
    for (int o = 16; o; o >>= 1) s += __shfl_xor_sync(~0u, s, o);
    if ((tid & 31) == 0) red[tid >> 5] = s;
    __syncthreads();
    if (tid == 0) {
        float t = 0.f;
#pragma unroll
        for (int i = 0; i < 8; ++i) t += red[i];
        g_memsq[row] = t;
    }
}

// ---------------- kernel 4: e4m3 mma.sync GEMM (f16 acc) + argmin + D write -
// CTA 128x64, 3-stage ring, 4 CTAs/SM target (2816 tiles / 592 slots = 95% eff).
// 8 warps (2M x 4N), warp tile 64x16. D stored f16.
__global__ void __launch_bounds__(256, 4) k_gemm() {
    extern __shared__ __align__(16) char dynsm[];
    __shared__ float s_msq[BN];

    int tid = threadIdx.x;
    int w = tid >> 5, lane = tid & 31;
    int warp_m = w & 1, warp_n = w >> 1;
    int p0 = blockIdx.x * BM, m0 = blockIdx.y * BN;

    if (tid < BN) s_msq[tid] = g_memsq[m0 + tid];

    uint32_t smbase = s2u(dynsm);

    // per-thread cp.async geometry
    int rowA = tid & 127, ccA = tid >> 7;          // A: 128 rows x 4 x 16B (2/thread)
    int rowB = tid & 63,  ccB = tid >> 6;          // B: 64 rows x 4 x 16B (1/thread)
    const uint8_t* gA = &g_A8[(size_t)(p0 + rowA) * KD + ccA * 16];
    const uint8_t* gB = &g_B8[(size_t)(m0 + rowB) * KD + ccB * 16];
    uint32_t dA0 = rowA * LDTB + ccA * 16;
    uint32_t dB0 = BM * LDTB + rowB * LDTB + ccB * 16;

    auto load_chunk = [&](int st, int k0) {        // 3 x 16B per thread
        uint32_t sb = smbase + st * STAGE_BYTES;
        const uint8_t* a = gA + k0;
        cpasync16(sb + dA0,      a);
        cpasync16(sb + dA0 + 32, a + 32);
        cpasync16(sb + dB0,      gB + k0);
        asm volatile("cp.async.commit_group;");
    };

    // ldmatrix byte offsets (16B segment = 16 fp8 k-values)
    uint32_t offA[4], offB;
#pragma unroll
    for (int fm = 0; fm < 4; ++fm)
        offA[fm] = (warp_m * 64 + fm * 16 + (lane & 15)) * LDTB + (lane >> 4) * 16;
    offB = BM * LDTB +
           (warp_n * 16 + (lane & 7) + ((lane >> 4) & 1) * 8) * LDTB +
           ((lane >> 3) & 1) * 16;

    uint32_t acc[4][2][2];                        // f16x2 pairs: 16 regs
#pragma unroll
    for (int fm = 0; fm < 4; ++fm)
#pragma unroll
        for (int fn = 0; fn < 2; ++fn) { acc[fm][fn][0] = 0u; acc[fm][fn][1] = 0u; }

    load_chunk(0, 0);
    load_chunk(1, BK);

    for (int kt = 0; kt < KSTEPS; ++kt) {
        if (kt + 1 < KSTEPS) asm volatile("cp.async.wait_group 1;");
        else                 asm volatile("cp.async.wait_group 0;");
        __syncthreads();                           // chunk kt visible; WAR safe
        if (kt + 2 < KSTEPS) load_chunk((kt + 2) % NSTAGE, (kt + 2) * BK);

        uint32_t sb = smbase + (kt % NSTAGE) * STAGE_BYTES;
#pragma unroll
        for (int ks = 0; ks < 2; ++ks) {           // two k32 halves of 64B row
            uint32_t b[4];
            ldsm4(b, sb + offB + ks * 32);
#pragma unroll
            for (int fm = 0; fm < 4; ++fm) {
                uint32_t a[4];
                ldsm4(a, sb + offA[fm] + ks * 32);
                mma16832h(acc[fm][0], a, &b[0]);
                mma16832h(acc[fm][1], a, &b[2]);
            }
        }
    }

    // register-direct epilogue: d = memsq - 2*score; store f16 pairs
    int q = lane & 3, rr = lane >> 2;
#pragma unroll
    for (int fm = 0; fm < 4; ++fm) {
        int pA = p0 + warp_m * 64 + fm * 16 + rr;
        int pB = pA + 8;
        bool vA = pA < NP, vB = pB < NP;
        ull keyA = ~0ull, keyB = ~0ull;
#pragma unroll
        for (int fn = 0; fn < 2; ++fn) {
            int nloc = warp_n * 16 + fn * 8 + q * 2;
            int mcol = m0 + nloc;
            float2 lo = __half22float2(*(const __half2*)&acc[fm][fn][0]);
            float2 hi = __half22float2(*(const __half2*)&acc[fm][fn][1]);
            float d0 = s_msq[nloc]     - 2.f * lo.x;
            float d1 = s_msq[nloc + 1] - 2.f * lo.y;
            float d2 = s_msq[nloc]     - 2.f * hi.x;
            float d3 = s_msq[nloc + 1] - 2.f * hi.y;
            keyA = min(keyA, min(mkkey(d0, mcol), mkkey(d1, mcol + 1)));
            keyB = min(keyB, min(mkkey(d2, mcol), mkkey(d3, mcol + 1)));
            if (vA) *(__half2*)&g_Dh[(size_t)pA * NM + mcol] = __floats2half2_rn(d0, d1);
            if (vB) *(__half2*)&g_Dh[(size_t)pB * NM + mcol] = __floats2half2_rn(d2, d3);
        }
#pragma unroll
        for (int o = 1; o < 4; o <<= 1) {
            keyA = min(keyA, __shfl_xor_sync(~0u, keyA, o));
            keyB = min(keyB, __shfl_xor_sync(~0u, keyB, o));
        }
        if (q == 0) {
            if (vA) atomicMin(&g_best[pA], keyA);
            if (vB) atomicMin(&g_best[pB], keyB);
        }
    }
}

// ---------------- kernel 5: exact rescore + recon row index -----------------
__global__ void k_rescore(const float* __restrict__ mem, const int* __restrict__ mapping) {
    __shared__ __align__(16) float s_patch[KD];
    __shared__ int s_cand[128];
    __shared__ int s_n;
    __shared__ float s_part[8];
    __shared__ ull s_bestk;

    int p = blockIdx.x;
    int tid = threadIdx.x;
    int i = p / LW, j = p - i * LW;
    for (int k = tid; k < KD; k += 256) {
        int c = k >> 10, rem = k & 1023, kh = rem >> 5, kw = rem & 31;
        s_patch[k] = g_xp[c * XPC + (i + kh) * XPW + j + kw];
    }
    if (tid == 0) { s_n = 0; s_bestk = ~0ull; }
    __syncthreads();

    float thr = fordinv((unsigned int)(g_best[p] >> 32)) + MARGIN + F16SLACK;
    const __half* Drow = &g_Dh[(size_t)p * NM];
    for (int m = tid; m < NM; m += 256) {
        if (__half2float(Drow[m]) < thr) {
            int pos = atomicAdd(&s_n, 1);
            if (pos < 128) s_cand[pos] = m;
        }
    }
    __syncthreads();
    int n = min(s_n, 128);
    for (int ci = 0; ci < n; ++ci) {
        int m = s_cand[ci];
        const float* mr = mem + (size_t)m * KD;
        float part = 0.f;
        for (int k = tid; k < KD; k += 256) part += s_patch[k] * mr[k];
#pragma unroll
        for (int o = 16; o; o >>= 1) part += __shfl_xor_sync(~0u, part, o);
        if ((tid & 31) == 0) s_part[tid >> 5] = part;
        __syncthreads();
        if (tid == 0) {
            float dot = 0.f;
#pragma unroll
            for (int w = 0; w < 8; ++w) dot += s_part[w];
            float d = g_memsq[m] - 2.f * dot;
            ull k = mkkey(d, m);
            if (k < s_bestk) s_bestk = k;
        }
        __syncthreads();
    }
    if (tid == 0) {
        g_bestx[p] = s_bestk;
        g_row[p] = mapping[(int)(s_bestk & 0xFFFFFFFFull)];
    }
}

// ---------------- kernel 6: overlap-add direct from mem2 + block max --------
__global__ void k_overlap(const float* __restrict__ mem2, float* __restrict__ out) {
    __shared__ __align__(16) float s[LW * 32];
    __shared__ float red[4][64];
    int bc = blockIdx.x;
    int c = bc >> 6, h = bc & 63;
    int r = h + 10;
    int tid = threadIdx.x;
    int w = tid & 63, grp = tid >> 6;
    int cc = w + 10;
    int jmin = max(0, cc - 31), jmax = min(LW - 1, cc);
    int ilo = max(0, r - 31), ihi = min(LW - 1, r);

    float sum = 0.f;
    for (int i = ilo; i <= ihi; ++i) {
        int kh = r - i;
        __syncthreads();
        for (int e = tid; e < LW * 8; e += 256) {
            int jj = e >> 3, q = e & 7;
            int mrow = g_row[i * LW + jj];
            *(float4*)&s[jj * 32 + q * 4] =
                *(const float4*)&mem2[(size_t)mrow * KD + c * 1024 + kh * 32 + q * 4];
        }
        __syncthreads();
        for (int jx = jmin + grp; jx <= jmax; jx += 4)
            sum += s[jx * 32 + (cc - jx)];
    }
    red[grp][w] = sum;
    __syncthreads();
    if (tid < 64) {
        float v = red[0][tid] + red[1][tid] + red[2][tid] + red[3][tid];
        out[(h * 64 + tid) * 3 + c] = v;
        red[0][tid] = v;
    }
    __syncthreads();
    if (tid == 0) {
        float mx = red[0][0];
        for (int t = 1; t < 64; ++t) mx = fmaxf(mx, red[0][t]);
        atomicMax(&g_maxord, ford(mx));
    }
}

// ---------------- kernel 7: normalize by global max -------------------------
__global__ void k_norm(float* __restrict__ out) {
    int idx = blockIdx.x * blockDim.x + threadIdx.x;
    if (idx < 64 * 64 * 3) out[idx] = out[idx] / fordinv(g_maxord);
}

// ---------------- launch -----------------------------------------------------
extern "C" void kernel_launch(void* const* d_in, const int* in_sizes, int n_in,
                              void* d_out, int out_size) {
    const float* img     = (const float*)d_in[0];
    const float* mem     = (const float*)d_in[1];
    const float* mem2    = (const float*)d_in[2];
    const int*   mapping = (const int*)d_in[3];
    float* out = (float*)d_out;

    cudaFuncSetAttribute(k_gemm, cudaFuncAttributeMaxDynamicSharedMemorySize, GEMM_SMEM);

    k_init<<<(3 * XPC + 255) / 256, 256>>>(img);
    k_buildA<<<(NPAD * (KD / 16) + 255) / 256, 256>>>();
    k_bconv<<<NM, 256>>>(mem);
    dim3 gg(NPAD / BM, NM / BN);
    k_gemm<<<gg, 256, GEMM_SMEM>>>();
    k_rescore<<<NP, 256>>>(mem, mapping);
    k_overlap<<<192, 256>>>(mem2, out);
    k_norm<<<48, 256>>>(out);
}

// round 16
// speedup vs baseline: 1.4113x; 1.4113x over previous
#include <cuda_runtime.h>
#include <cuda_bf16.h>
#include <cuda_fp16.h>
#include <cstdint>

typedef unsigned long long ull;

#define NP 2809          // 53*53 patches
#define NPAD 2816        // 22*128
#define LW 53
#define NM 8192          // memories
#define KD 3072          // 3*32*32
#define XPW 84
#define XPC 7056         // 84*84
#define MARGIN 48.0f
#define F16SLACK 8.0f    // f16 D-storage rounding slack for candidate select
#define QSCALE 16.0f     // int8 quantization scale
#define DSCALE (2.0f / (QSCALE * QSCALE))   // 2/256

#define BM 128
#define BN 128
#define BK 64              // int8 elements per K-chunk (64 bytes/row)
#define KSTEPS (KD / BK)   // 48
#define LDTB 80            // smem row stride in BYTES (64 + 16 pad, conflict-free)
#define STAGE_BYTES ((BM + BN) * LDTB)      // 20480
#define NSTAGE 3
#define GEMM_SMEM (NSTAGE * STAGE_BYTES)    // 61440

// ---------------- scratch (device globals; no allocations allowed) ----------
__device__ __align__(16) float g_xp[3 * XPC];
__device__ float g_memsq[NM];
__device__ ull   g_best[NP];                    // approx (pass1) key
__device__ ull   g_bestx[NP];                   // exact (rescore) key
__device__ int   g_row[NP];                     // mapping[nn] per patch
__device__ __align__(16) __half g_Dh[(size_t)NP * NM];     // ~46 MB approx distances (f16)
__device__ __align__(16) uint8_t g_A8[(size_t)NPAD * KD];  // 8.7 MB  s8 patches
__device__ __align__(16) uint8_t g_B8[(size_t)NM * KD];    // 25 MB   s8 memories
__device__ unsigned int g_maxord;

// ---------------- helpers ---------------------------------------------------
__device__ __forceinline__ unsigned int ford(float f) {
    unsigned int u = __float_as_uint(f);
    return (u & 0x80000000u) ? ~u : (u | 0x80000000u);
}
__device__ __forceinline__ float fordinv(unsigned int o) {
    unsigned int u = (o & 0x80000000u) ? (o ^ 0x80000000u) : ~o;
    return __uint_as_float(u);
}
__device__ __forceinline__ ull mkkey(float d, int m) {
    return ((ull)ford(d) << 32) | (unsigned int)m;
}
__device__ __forceinline__ uint32_t s2u(const void* p) {
    uint32_t a;
    asm("{ .reg .u64 t; cvta.to.shared.u64 t, %1; cvt.u32.u64 %0, t; }" : "=r"(a) : "l"(p));
    return a;
}
__device__ __forceinline__ int q8(float x) {
    int q = __float2int_rn(x * QSCALE);
    return max(-127, min(127, q));
}
__device__ __forceinline__ uint32_t pack4_s8(float x0, float x1, float x2, float x3) {
    return (uint32_t)(q8(x0) & 0xFF) | ((uint32_t)(q8(x1) & 0xFF) << 8) |
           ((uint32_t)(q8(x2) & 0xFF) << 16) | ((uint32_t)(q8(x3) & 0xFF) << 24);
}
__device__ __forceinline__ void ldsm4(uint32_t* r, uint32_t addr) {
    asm volatile("ldmatrix.sync.aligned.m8n8.x4.shared.b16 {%0,%1,%2,%3}, [%4];"
                 : "=r"(r[0]), "=r"(r[1]), "=r"(r[2]), "=r"(r[3]) : "r"(addr));
}
// int8 IMMA: s8 x s8 -> s32 accumulate
__device__ __forceinline__ void mma16832i(int* d, const uint32_t* a, const uint32_t* b) {
    asm volatile("mma.sync.aligned.m16n8k32.row.col.s32.s8.s8.s32 "
                 "{%0,%1,%2,%3}, {%4,%5,%6,%7}, {%8,%9}, {%0,%1,%2,%3};"
                 : "+r"(d[0]), "+r"(d[1]), "+r"(d[2]), "+r"(d[3])
                 : "r"(a[0]), "r"(a[1]), "r"(a[2]), "r"(a[3]), "r"(b[0]), "r"(b[1]));
}
__device__ __forceinline__ void cpasync16(uint32_t dst, const void* src) {
    asm volatile("cp.async.cg.shared.global [%0], [%1], 16;" :: "r"(dst), "l"(src));
}

// ---------------- kernel 1: build padded image + init -----------------------
__global__ void k_init(const float* __restrict__ img) {
    int idx = blockIdx.x * blockDim.x + threadIdx.x;
    if (idx < 3 * XPC) {
        int c = idx / XPC, rem = idx - c * XPC;
        int r = rem / XPW, col = rem - r * XPW;
        int h = r - 10, w = col - 10;
        float v = 0.f;
        if ((unsigned)h < 64u && (unsigned)w < 64u) v = img[(h * 64 + w) * 3 + c];
        g_xp[idx] = v;
    }
    if (idx < NP) g_best[idx] = ~0ull;
    if (idx == 0) g_maxord = 0u;
}

// ---------------- kernel 2: build s8 A matrix (patches) ---------------------
__global__ void k_buildA() {
    int e = blockIdx.x * blockDim.x + threadIdx.x;   // NPAD * (KD/16)
    if (e >= NPAD * (KD / 16)) return;
    int m = e / (KD / 16), r = e - m * (KD / 16);
    int k = r * 16;
    uint32_t w0 = 0, w1 = 0, w2 = 0, w3 = 0;
    if (m < NP) {
        int i = m / LW, j = m - i * LW;
        int c = k >> 10, rem = k & 1023, kh = rem >> 5, kw = rem & 31;
        const float* src = &g_xp[c * XPC + (i + kh) * XPW + j + kw];
        w0 = pack4_s8(src[0],  src[1],  src[2],  src[3]);
        w1 = pack4_s8(src[4],  src[5],  src[6],  src[7]);
        w2 = pack4_s8(src[8],  src[9],  src[10], src[11]);
        w3 = pack4_s8(src[12], src[13], src[14], src[15]);
    }
    *(uint4*)&g_A8[(size_t)m * KD + k] = make_uint4(w0, w1, w2, w3);
}

// ---------------- kernel 3: convert mem to s8 + fused row squared norms -----
__global__ void __launch_bounds__(256) k_bconv(const float* __restrict__ mem) {
    __shared__ float red[8];
    int row = blockIdx.x, tid = threadIdx.x;
    const float4* src = (const float4*)(mem + (size_t)row * KD);
    float s = 0.f;
#pragma unroll
    for (int t = 0; t < 3; ++t) {                 // 3*256*4 = 3072
        int e = tid + t * 256;
        float4 v = src[e];
        *(uint32_t*)&g_B8[(size_t)row * KD + e * 4] = pack4_s8(v.x, v.y, v.z, v.w);
        s += v.x * v.x + v.y * v.y + v.z * v.z + v.w * v.w;
    }
#pragma unroll
    for (int o = 16; o; o >>= 1) s += __shfl_xor_sync(~0u, s, o);
    if ((tid & 31) == 0) red[tid >> 5] = s;
    __syncthreads();
    if (tid == 0) {
        float t = 0.f;
#pragma unroll
        for (int i = 0; i < 8; ++i) t += red[i];
        g_memsq[row] = t;
    }
}

// ---------------- kernel 4: s8 IMMA GEMM + argmin + f16 D write -------------
// CTA 128x128, 3-stage ring, 2 CTAs/SM (s32 acc = 64 regs, simple ldsm loop).
// 8 warps (2M x 4N), warp tile 64x32. d = memsq - dot * 2/256.
__global__ void __launch_bounds__(256, 2) k_gemm() {
    extern __shared__ __align__(16) char dynsm[];
    __shared__ float s_msq[BN];

    int tid = threadIdx.x;
    int w = tid >> 5, lane = tid & 31;
    int warp_m = w & 1, warp_n = w >> 1;
    int p0 = blockIdx.x * BM, m0 = blockIdx.y * BN;

    if (tid < BN) s_msq[tid] = g_memsq[m0 + tid];

    uint32_t smbase = s2u(dynsm);

    // per-thread cp.async geometry: row = tid&127, 16B column cc0 = tid>>7
    int row = tid & 127, cc0 = tid >> 7;
    const uint8_t* gA = &g_A8[(size_t)(p0 + row) * KD + cc0 * 16];
    const uint8_t* gB = &g_B8[(size_t)(m0 + row) * KD + cc0 * 16];
    uint32_t dA0 = row * LDTB + cc0 * 16;
    uint32_t dB0 = BM * LDTB + row * LDTB + cc0 * 16;

    auto load_chunk = [&](int st, int k0) {       // 4 x 16B per thread
        uint32_t sb = smbase + st * STAGE_BYTES;
        const uint8_t* a = gA + k0;
        const uint8_t* b = gB + k0;
        cpasync16(sb + dA0,      a);
        cpasync16(sb + dA0 + 32, a + 32);
        cpasync16(sb + dB0,      b);
        cpasync16(sb + dB0 + 32, b + 32);
        asm volatile("cp.async.commit_group;");
    };

    // ldmatrix byte offsets (16B segment = 16 s8 k-values)
    uint32_t offA[4], offB[2];
#pragma unroll
    for (int fm = 0; fm < 4; ++fm)
        offA[fm] = (warp_m * 64 + fm * 16 + (lane & 15)) * LDTB + (lane >> 4) * 16;
#pragma unroll
    for (int fb = 0; fb < 2; ++fb)
        offB[fb] = BM * LDTB +
                   (warp_n * 32 + fb * 16 + (lane & 7) + ((lane >> 4) & 1) * 8) * LDTB +
                   ((lane >> 3) & 1) * 16;

    int acc[4][4][4];                             // s32: 64 regs
#pragma unroll
    for (int fm = 0; fm < 4; ++fm)
#pragma unroll
        for (int fn = 0; fn < 4; ++fn)
#pragma unroll
            for (int q = 0; q < 4; ++q) acc[fm][fn][q] = 0;

    load_chunk(0, 0);
    load_chunk(1, BK);

    for (int kt = 0; kt < KSTEPS; ++kt) {
        if (kt + 1 < KSTEPS) asm volatile("cp.async.wait_group 1;");
        else                 asm volatile("cp.async.wait_group 0;");
        __syncthreads();                           // chunk kt visible; WAR safe
        if (kt + 2 < KSTEPS) load_chunk((kt + 2) % NSTAGE, (kt + 2) * BK);

        uint32_t sb = smbase + (kt % NSTAGE) * STAGE_BYTES;
#pragma unroll
        for (int ks = 0; ks < 2; ++ks) {           // two k32 halves of 64B row
            uint32_t b[2][4];
            ldsm4(b[0], sb + offB[0] + ks * 32);
            ldsm4(b[1], sb + offB[1] + ks * 32);
#pragma unroll
            for (int fm = 0; fm < 4; ++fm) {
                uint32_t a[4];
                ldsm4(a, sb + offA[fm] + ks * 32);
                mma16832i(acc[fm][0], a, &b[0][0]);
                mma16832i(acc[fm][1], a, &b[0][2]);
                mma16832i(acc[fm][2], a, &b[1][0]);
                mma16832i(acc[fm][3], a, &b[1][2]);
            }
        }
    }

    // register-direct epilogue: d = memsq - dot * 2/256; store f16 pairs
    int q = lane & 3, rr = lane >> 2;
#pragma unroll
    for (int fm = 0; fm < 4; ++fm) {
        int pA = p0 + warp_m * 64 + fm * 16 + rr;
        int pB = pA + 8;
        bool vA = pA < NP, vB = pB < NP;
        ull keyA = ~0ull, keyB = ~0ull;
#pragma unroll
        for (int fn = 0; fn < 4; ++fn) {
            int nloc = warp_n * 32 + fn * 8 + q * 2;
            int mcol = m0 + nloc;
            float d0 = s_msq[nloc]     - DSCALE * (float)acc[fm][fn][0];
            float d1 = s_msq[nloc + 1] - DSCALE * (float)acc[fm][fn][1];
            float d2 = s_msq[nloc]     - DSCALE * (float)acc[fm][fn][2];
            float d3 = s_msq[nloc + 1] - DSCALE * (float)acc[fm][fn][3];
            keyA = min(keyA, min(mkkey(d0, mcol), mkkey(d1, mcol + 1)));
            keyB = min(keyB, min(mkkey(d2, mcol), mkkey(d3, mcol + 1)));
            if (vA) *(__half2*)&g_Dh[(size_t)pA * NM + mcol] = __floats2half2_rn(d0, d1);
            if (vB) *(__half2*)&g_Dh[(size_t)pB * NM + mcol] = __floats2half2_rn(d2, d3);
        }
#pragma unroll
        for (int o = 1; o < 4; o <<= 1) {
            keyA = min(keyA, __shfl_xor_sync(~0u, keyA, o));
            keyB = min(keyB, __shfl_xor_sync(~0u, keyB, o));
        }
        if (q == 0) {
            if (vA) atomicMin(&g_best[pA], keyA);
            if (vB) atomicMin(&g_best[pB], keyB);
        }
    }
}

// ---------------- kernel 5: exact rescore + recon row index -----------------
__global__ void k_rescore(const float* __restrict__ mem, const int* __restrict__ mapping) {
    __shared__ __align__(16) float s_patch[KD];
    __shared__ int s_cand[128];
    __shared__ int s_n;
    __shared__ float s_part[8];
    __shared__ ull s_bestk;

    int p = blockIdx.x;
    int tid = threadIdx.x;
    int i = p / LW, j = p - i * LW;
    for (int k = tid; k < KD; k += 256) {
        int c = k >> 10, rem = k & 1023, kh = rem >> 5, kw = rem & 31;
        s_patch[k] = g_xp[c * XPC + (i + kh) * XPW + j + kw];
    }
    if (tid == 0) { s_n = 0; s_bestk = ~0ull; }
    __syncthreads();

    float thr = fordinv((unsigned int)(g_best[p] >> 32)) + MARGIN + F16SLACK;
    const __half* Drow = &g_Dh[(size_t)p * NM];
    for (int m = tid; m < NM; m += 256) {
        if (__half2float(Drow[m]) < thr) {
            int pos = atomicAdd(&s_n, 1);
            if (pos < 128) s_cand[pos] = m;
        }
    }
    __syncthreads();
    int n = min(s_n, 128);
    for (int ci = 0; ci < n; ++ci) {
        int m = s_cand[ci];
        const float* mr = mem + (size_t)m * KD;
        float part = 0.f;
        for (int k = tid; k < KD; k += 256) part += s_patch[k] * mr[k];
#pragma unroll
        for (int o = 16; o; o >>= 1) part += __shfl_xor_sync(~0u, part, o);
        if ((tid & 31) == 0) s_part[tid >> 5] = part;
        __syncthreads();
        if (tid == 0) {
            float dot = 0.f;
#pragma unroll
            for (int w = 0; w < 8; ++w) dot += s_part[w];
            float d = g_memsq[m] - 2.f * dot;
            ull k = mkkey(d, m);
            if (k < s_bestk) s_bestk = k;
        }
        __syncthreads();
    }
    if (tid == 0) {
        g_bestx[p] = s_bestk;
        g_row[p] = mapping[(int)(s_bestk & 0xFFFFFFFFull)];
    }
}

// ---------------- kernel 6: overlap-add direct from mem2 + block max --------
__global__ void k_overlap(const float* __restrict__ mem2, float* __restrict__ out) {
    __shared__ __align__(16) float s[LW * 32];
    __shared__ float red[4][64];
    int bc = blockIdx.x;
    int c = bc >> 6, h = bc & 63;
    int r = h + 10;
    int tid = threadIdx.x;
    int w = tid & 63, grp = tid >> 6;
    int cc = w + 10;
    int jmin = max(0, cc - 31), jmax = min(LW - 1, cc);
    int ilo = max(0, r - 31), ihi = min(LW - 1, r);

    float sum = 0.f;
    for (int i = ilo; i <= ihi; ++i) {
        int kh = r - i;
        __syncthreads();
        for (int e = tid; e < LW * 8; e += 256) {
            int jj = e >> 3, q = e & 7;
            int mrow = g_row[i * LW + jj];
            *(float4*)&s[jj * 32 + q * 4] =
                *(const float4*)&mem2[(size_t)mrow * KD + c * 1024 + kh * 32 + q * 4];
        }
        __syncthreads();
        for (int jx = jmin + grp; jx <= jmax; jx += 4)
            sum += s[jx * 32 + (cc - jx)];
    }
    red[grp][w] = sum;
    __syncthreads();
    if (tid < 64) {
        float v = red[0][tid] + red[1][tid] + red[2][tid] + red[3][tid];
        out[(h * 64 + tid) * 3 + c] = v;
        red[0][tid] = v;
    }
    __syncthreads();
    if (tid == 0) {
        float mx = red[0][0];
        for (int t = 1; t < 64; ++t) mx = fmaxf(mx, red[0][t]);
        atomicMax(&g_maxord, ford(mx));
    }
}

// ---------------- kernel 7: normalize by global max -------------------------
__global__ void k_norm(float* __restrict__ out) {
    int idx = blockIdx.x * blockDim.x + threadIdx.x;
    if (idx < 64 * 64 * 3) out[idx] = out[idx] / fordinv(g_maxord);
}

// ---------------- launch -----------------------------------------------------
extern "C" void kernel_launch(void* const* d_in, const int* in_sizes, int n_in,
                              void* d_out, int out_size) {
    const float* img     = (const float*)d_in[0];
    const float* mem     = (const float*)d_in[1];
    const float* mem2    = (const float*)d_in[2];
    const int*   mapping = (const int*)d_in[3];
    float* out = (float*)d_out;

    cudaFuncSetAttribute(k_gemm, cudaFuncAttributeMaxDynamicSharedMemorySize, GEMM_SMEM);

    k_init<<<(3 * XPC + 255) / 256, 256>>>(img);
    k_buildA<<<(NPAD * (KD / 16) + 255) / 256, 256>>>();
    k_bconv<<<NM, 256>>>(mem);
    dim3 gg(NPAD / BM, NM / BN);
    k_gemm<<<gg, 256, GEMM_SMEM>>>();
    k_rescore<<<NP, 256>>>(mem, mapping);
    k_overlap<<<192, 256>>>(mem2, out);
    k_norm<<<48, 256>>>(out);
}

// round 17
// speedup vs baseline: 1.6515x; 1.1701x over previous
#include <cuda_runtime.h>
#include <cuda_bf16.h>
#include <cuda_fp16.h>
#include <cstdint>

typedef unsigned long long ull;

#define NP 2809          // 53*53 patches
#define NPAD 2816        // 22*128
#define LW 53
#define NM 8192          // memories
#define KD 3072          // 3*32*32
#define XPW 84
#define XPC 7056         // 84*84
#define MARGIN 48.0f
#define F16SLACK 8.0f    // f16 D-storage rounding slack for candidate select
#define QSCALE 16.0f     // int8 quantization scale
#define DSCALE (2.0f / (QSCALE * QSCALE))   // 2/256

#define BM 128
#define BN 256
#define BK 64              // int8 elements per K-chunk (64 bytes/row)
#define KSTEPS (KD / BK)   // 48
#define LDTB 80            // smem row stride in BYTES (64 + 16 pad, conflict-free)
#define STAGE_BYTES ((BM + BN) * LDTB)      // 30720
#define NSTAGE 3
#define GEMM_SMEM (NSTAGE * STAGE_BYTES)    // 92160

// ---------------- scratch (device globals; no allocations allowed) ----------
__device__ __align__(16) float g_xp[3 * XPC];
__device__ float g_memsq[NM];
__device__ ull   g_best[NP];                    // approx (pass1) key
__device__ ull   g_bestx[NP];                   // exact (rescore) key
__device__ int   g_row[NP];                     // mapping[nn] per patch
__device__ __align__(16) __half g_Dh[(size_t)NP * NM];     // ~46 MB approx distances (f16)
__device__ __align__(16) uint8_t g_A8[(size_t)NPAD * KD];  // 8.7 MB  s8 patches
__device__ __align__(16) uint8_t g_B8[(size_t)NM * KD];    // 25 MB   s8 memories
__device__ unsigned int g_maxord;

// ---------------- helpers ---------------------------------------------------
__device__ __forceinline__ unsigned int ford(float f) {
    unsigned int u = __float_as_uint(f);
    return (u & 0x80000000u) ? ~u : (u | 0x80000000u);
}
__device__ __forceinline__ float fordinv(unsigned int o) {
    unsigned int u = (o & 0x80000000u) ? (o ^ 0x80000000u) : ~o;
    return __uint_as_float(u);
}
__device__ __forceinline__ ull mkkey(float d, int m) {
    return ((ull)ford(d) << 32) | (unsigned int)m;
}
__device__ __forceinline__ uint32_t s2u(const void* p) {
    uint32_t a;
    asm("{ .reg .u64 t; cvta.to.shared.u64 t, %1; cvt.u32.u64 %0, t; }" : "=r"(a) : "l"(p));
    return a;
}
__device__ __forceinline__ int q8(float x) {
    int q = __float2int_rn(x * QSCALE);
    return max(-127, min(127, q));
}
__device__ __forceinline__ uint32_t pack4_s8(float x0, float x1, float x2, float x3) {
    return (uint32_t)(q8(x0) & 0xFF) | ((uint32_t)(q8(x1) & 0xFF) << 8) |
           ((uint32_t)(q8(x2) & 0xFF) << 16) | ((uint32_t)(q8(x3) & 0xFF) << 24);
}
__device__ __forceinline__ void ldsm4(uint32_t* r, uint32_t addr) {
    asm volatile("ldmatrix.sync.aligned.m8n8.x4.shared.b16 {%0,%1,%2,%3}, [%4];"
                 : "=r"(r[0]), "=r"(r[1]), "=r"(r[2]), "=r"(r[3]) : "r"(addr));
}
// int8 IMMA: s8 x s8 -> s32 accumulate
__device__ __forceinline__ void mma16832i(int* d, const uint32_t* a, const uint32_t* b) {
    asm volatile("mma.sync.aligned.m16n8k32.row.col.s32.s8.s8.s32 "
                 "{%0,%1,%2,%3}, {%4,%5,%6,%7}, {%8,%9}, {%0,%1,%2,%3};"
                 : "+r"(d[0]), "+r"(d[1]), "+r"(d[2]), "+r"(d[3])
                 : "r"(a[0]), "r"(a[1]), "r"(a[2]), "r"(a[3]), "r"(b[0]), "r"(b[1]));
}
__device__ __forceinline__ void cpasync16(uint32_t dst, const void* src) {
    asm volatile("cp.async.cg.shared.global [%0], [%1], 16;" :: "r"(dst), "l"(src));
}

// ---------------- kernel 1: build padded image + init -----------------------
__global__ void k_init(const float* __restrict__ img) {
    int idx = blockIdx.x * blockDim.x + threadIdx.x;
    if (idx < 3 * XPC) {
        int c = idx / XPC, rem = idx - c * XPC;
        int r = rem / XPW, col = rem - r * XPW;
        int h = r - 10, w = col - 10;
        float v = 0.f;
        if ((unsigned)h < 64u && (unsigned)w < 64u) v = img[(h * 64 + w) * 3 + c];
        g_xp[idx] = v;
    }
    if (idx < NP) g_best[idx] = ~0ull;
    if (idx == 0) g_maxord = 0u;
}

// ---------------- kernel 2: build s8 A matrix (patches) ---------------------
__global__ void k_buildA() {
    int e = blockIdx.x * blockDim.x + threadIdx.x;   // NPAD * (KD/16)
    if (e >= NPAD * (KD / 16)) return;
    int m = e / (KD / 16), r = e - m * (KD / 16);
    int k = r * 16;
    uint32_t w0 = 0, w1 = 0, w2 = 0, w3 = 0;
    if (m < NP) {
        int i = m / LW, j = m - i * LW;
        int c = k >> 10, rem = k & 1023, kh = rem >> 5, kw = rem & 31;
        const float* src = &g_xp[c * XPC + (i + kh) * XPW + j + kw];
        w0 = pack4_s8(src[0],  src[1],  src[2],  src[3]);
        w1 = pack4_s8(src[4],  src[5],  src[6],  src[7]);
        w2 = pack4_s8(src[8],  src[9],  src[10], src[11]);
        w3 = pack4_s8(src[12], src[13], src[14], src[15]);
    }
    *(uint4*)&g_A8[(size_t)m * KD + k] = make_uint4(w0, w1, w2, w3);
}

// ---------------- kernel 3: convert mem to s8 + fused row squared norms -----
__global__ void __launch_bounds__(256) k_bconv(const float* __restrict__ mem) {
    __shared__ float red[8];
    int row = blockIdx.x, tid = threadIdx.x;
    const float4* src = (const float4*)(mem + (size_t)row * KD);
    float s = 0.f;
#pragma unroll
    for (int t = 0; t < 3; ++t) {                 // 3*256*4 = 3072
        int e = tid + t * 256;
        float4 v = src[e];
        *(uint32_t*)&g_B8[(size_t)row * KD + e * 4] = pack4_s8(v.x, v.y, v.z, v.w);
        s += v.x * v.x + v.y * v.y + v.z * v.z + v.w * v.w;
    }
#pragma unroll
    for (int o = 16; o; o >>= 1) s += __shfl_xor_sync(~0u, s, o);
    if ((tid & 31) == 0) red[tid >> 5] = s;
    __syncthreads();
    if (tid == 0) {
        float t = 0.f;
#pragma unroll
        for (int i = 0; i < 8; ++i) t += red[i];
        g_memsq[row] = t;
    }
}

// ---------------- kernel 4: s8 IMMA GEMM + argmin + f16 D write -------------
// CTA 128x256, 512 threads (16 warps, 2M x 8N, warp 64x32), 3-stage ring,
// 1 CTA/SM, 95% wave eff. A-frag parity pipeline. d = memsq - dot * 2/256.
__global__ void __launch_bounds__(512, 1) k_gemm() {
    extern __shared__ __align__(16) char dynsm[];
    __shared__ float s_msq[BN];

    int tid = threadIdx.x;
    int w = tid >> 5, lane = tid & 31;
    int warp_m = w & 1, warp_n = w >> 1;          // warp_n 0..7
    int p0 = blockIdx.x * BM, m0 = blockIdx.y * BN;

    if (tid < BN) s_msq[tid] = g_memsq[m0 + tid];

    uint32_t smbase = s2u(dynsm);

    // per-thread cp.async geometry
    int rowA = tid & 127, ccA = tid >> 7;          // A: 512 x 16B chunks (1/thread)
    const uint8_t* gA = &g_A8[(size_t)(p0 + rowA) * KD + ccA * 16];
    uint32_t dA0 = rowA * LDTB + ccA * 16;
    int rowB0 = tid >> 2, ccB = tid & 3;           // B: 1024 chunks (2/thread)
    const uint8_t* gB0 = &g_B8[(size_t)(m0 + rowB0) * KD + ccB * 16];
    const uint8_t* gB1 = &g_B8[(size_t)(m0 + rowB0 + 128) * KD + ccB * 16];
    uint32_t dB0 = BM * LDTB + rowB0 * LDTB + ccB * 16;
    uint32_t dB1 = BM * LDTB + (rowB0 + 128) * LDTB + ccB * 16;

    auto load_chunk = [&](int st, int k0) {       // 3 x 16B per thread
        uint32_t sb = smbase + st * STAGE_BYTES;
        cpasync16(sb + dA0, gA + k0);
        cpasync16(sb + dB0, gB0 + k0);
        cpasync16(sb + dB1, gB1 + k0);
        asm volatile("cp.async.commit_group;");
    };

    // ldmatrix byte offsets (16B segment = 16 s8 k-values)
    uint32_t offA[4], offB[2];
#pragma unroll
    for (int fm = 0; fm < 4; ++fm)
        offA[fm] = (warp_m * 64 + fm * 16 + (lane & 15)) * LDTB + (lane >> 4) * 16;
#pragma unroll
    for (int fb = 0; fb < 2; ++fb)
        offB[fb] = BM * LDTB +
                   (warp_n * 32 + fb * 16 + (lane & 7) + ((lane >> 4) & 1) * 8) * LDTB +
                   ((lane >> 3) & 1) * 16;

    int acc[4][4][4];                             // s32: 64 regs
#pragma unroll
    for (int fm = 0; fm < 4; ++fm)
#pragma unroll
        for (int fn = 0; fn < 4; ++fn)
#pragma unroll
            for (int q = 0; q < 4; ++q) acc[fm][fn][q] = 0;

    load_chunk(0, 0);
    load_chunk(1, BK);

    for (int kt = 0; kt < KSTEPS; ++kt) {
        if (kt + 1 < KSTEPS) asm volatile("cp.async.wait_group 1;");
        else                 asm volatile("cp.async.wait_group 0;");
        __syncthreads();                           // chunk kt visible; WAR safe
        if (kt + 2 < KSTEPS) load_chunk((kt + 2) % NSTAGE, (kt + 2) * BK);

        uint32_t sb = smbase + (kt % NSTAGE) * STAGE_BYTES;
#pragma unroll
        for (int ks = 0; ks < 2; ++ks) {           // two k32 halves of 64B row
            uint32_t b[2][4];
            ldsm4(b[0], sb + offB[0] + ks * 32);
            ldsm4(b[1], sb + offB[1] + ks * 32);
            uint32_t af[2][4];                     // A-frag parity pipeline
            ldsm4(af[0], sb + offA[0] + ks * 32);
#pragma unroll
            for (int fm = 0; fm < 4; ++fm) {
                int cur = fm & 1;
                if (fm < 3) ldsm4(af[cur ^ 1], sb + offA[fm + 1] + ks * 32);
                mma16832i(acc[fm][0], af[cur], &b[0][0]);
                mma16832i(acc[fm][1], af[cur], &b[0][2]);
                mma16832i(acc[fm][2], af[cur], &b[1][0]);
                mma16832i(acc[fm][3], af[cur], &b[1][2]);
            }
        }
    }

    // register-direct epilogue: d = memsq - dot * 2/256; store f16 pairs
    int q = lane & 3, rr = lane >> 2;
#pragma unroll
    for (int fm = 0; fm < 4; ++fm) {
        int pA = p0 + warp_m * 64 + fm * 16 + rr;
        int pB = pA + 8;
        bool vA = pA < NP, vB = pB < NP;
        ull keyA = ~0ull, keyB = ~0ull;
#pragma unroll
        for (int fn = 0; fn < 4; ++fn) {
            int nloc = warp_n * 32 + fn * 8 + q * 2;
            int mcol = m0 + nloc;
            float d0 = s_msq[nloc]     - DSCALE * (float)acc[fm][fn][0];
            float d1 = s_msq[nloc + 1] - DSCALE * (float)acc[fm][fn][1];
            float d2 = s_msq[nloc]     - DSCALE * (float)acc[fm][fn][2];
            float d3 = s_msq[nloc + 1] - DSCALE * (float)acc[fm][fn][3];
            keyA = min(keyA, min(mkkey(d0, mcol), mkkey(d1, mcol + 1)));
            keyB = min(keyB, min(mkkey(d2, mcol), mkkey(d3, mcol + 1)));
            if (vA) *(__half2*)&g_Dh[(size_t)pA * NM + mcol] = __floats2half2_rn(d0, d1);
            if (vB) *(__half2*)&g_Dh[(size_t)pB * NM + mcol] = __floats2half2_rn(d2, d3);
        }
#pragma unroll
        for (int o = 1; o < 4; o <<= 1) {
            keyA = min(keyA, __shfl_xor_sync(~0u, keyA, o));
            keyB = min(keyB, __shfl_xor_sync(~0u, keyB, o));
        }
        if (q == 0) {
            if (vA) atomicMin(&g_best[pA], keyA);
            if (vB) atomicMin(&g_best[pB], keyB);
        }
    }
}

// ---------------- kernel 5: exact rescore + recon row index -----------------
__global__ void k_rescore(const float* __restrict__ mem, const int* __restrict__ mapping) {
    __shared__ __align__(16) float s_patch[KD];
    __shared__ int s_cand[128];
    __shared__ int s_n;
    __shared__ float s_part[8];
    __shared__ ull s_bestk;

    int p = blockIdx.x;
    int tid = threadIdx.x;
    int i = p / LW, j = p - i * LW;
    for (int k = tid; k < KD; k += 256) {
        int c = k >> 10, rem = k & 1023, kh = rem >> 5, kw = rem & 31;
        s_patch[k] = g_xp[c * XPC + (i + kh) * XPW + j + kw];
    }
    if (tid == 0) { s_n = 0; s_bestk = ~0ull; }
    __syncthreads();

    float thr = fordinv((unsigned int)(g_best[p] >> 32)) + MARGIN + F16SLACK;
    const __half* Drow = &g_Dh[(size_t)p * NM];
    for (int m = tid; m < NM; m += 256) {
        if (__half2float(Drow[m]) < thr) {
            int pos = atomicAdd(&s_n, 1);
            if (pos < 128) s_cand[pos] = m;
        }
    }
    __syncthreads();
    int n = min(s_n, 128);
    for (int ci = 0; ci < n; ++ci) {
        int m = s_cand[ci];
        const float* mr = mem + (size_t)m * KD;
        float part = 0.f;
        for (int k = tid; k < KD; k += 256) part += s_patch[k] * mr[k];
#pragma unroll
        for (int o = 16; o; o >>= 1) part += __shfl_xor_sync(~0u, part, o);
        if ((tid & 31) == 0) s_part[tid >> 5] = part;
        __syncthreads();
        if (tid == 0) {
            float dot = 0.f;
#pragma unroll
            for (int w = 0; w < 8; ++w) dot += s_part[w];
            float d = g_memsq[m] - 2.f * dot;
            ull k = mkkey(d, m);
            if (k < s_bestk) s_bestk = k;
        }
        __syncthreads();
    }
    if (tid == 0) {
        g_bestx[p] = s_bestk;
        g_row[p] = mapping[(int)(s_bestk & 0xFFFFFFFFull)];
    }
}

// ---------------- kernel 6: overlap-add direct from mem2 + block max --------
__global__ void k_overlap(const float* __restrict__ mem2, float* __restrict__ out) {
    __shared__ __align__(16) float s[LW * 32];
    __shared__ float red[4][64];
    int bc = blockIdx.x;
    int c = bc >> 6, h = bc & 63;
    int r = h + 10;
    int tid = threadIdx.x;
    int w = tid & 63, grp = tid >> 6;
    int cc = w + 10;
    int jmin = max(0, cc - 31), jmax = min(LW - 1, cc);
    int ilo = max(0, r - 31), ihi = min(LW - 1, r);

    float sum = 0.f;
    for (int i = ilo; i <= ihi; ++i) {
        int kh = r - i;
        __syncthreads();
        for (int e = tid; e < LW * 8; e += 256) {
            int jj = e >> 3, q = e & 7;
            int mrow = g_row[i * LW + jj];
            *(float4*)&s[jj * 32 + q * 4] =
                *(const float4*)&mem2[(size_t)mrow * KD + c * 1024 + kh * 32 + q * 4];
        }
        __syncthreads();
        for (int jx = jmin + grp; jx <= jmax; jx += 4)
            sum += s[jx * 32 + (cc - jx)];
    }
    red[grp][w] = sum;
    __syncthreads();
    if (tid < 64) {
        float v = red[0][tid] + red[1][tid] + red[2][tid] + red[3][tid];
        out[(h * 64 + tid) * 3 + c] = v;
        red[0][tid] = v;
    }
    __syncthreads();
    if (tid == 0) {
        float mx = red[0][0];
        for (int t = 1; t < 64; ++t) mx = fmaxf(mx, red[0][t]);
        atomicMax(&g_maxord, ford(mx));
    }
}

// ---------------- kernel 7: normalize by global max -------------------------
__global__ void k_norm(float* __restrict__ out) {
    int idx = blockIdx.x * blockDim.x + threadIdx.x;
    if (idx < 64 * 64 * 3) out[idx] = out[idx] / fordinv(g_maxord);
}

// ---------------- launch -----------------------------------------------------
extern "C" void kernel_launch(void* const* d_in, const int* in_sizes, int n_in,
                              void* d_out, int out_size) {
    const float* img     = (const float*)d_in[0];
    const float* mem     = (const float*)d_in[1];
    const float* mem2    = (const float*)d_in[2];
    const int*   mapping = (const int*)d_in[3];
    float* out = (float*)d_out;

    cudaFuncSetAttribute(k_gemm, cudaFuncAttributeMaxDynamicSharedMemorySize, GEMM_SMEM);

    k_init<<<(3 * XPC + 255) / 256, 256>>>(img);
    k_buildA<<<(NPAD * (KD / 16) + 255) / 256, 256>>>();
    k_bconv<<<NM, 256>>>(mem);
    dim3 gg(NPAD / BM, NM / BN);
    k_gemm<<<gg, 512, GEMM_SMEM>>>();
    k_rescore<<<NP, 256>>>(mem, mapping);
    k_overlap<<<192, 256>>>(mem2, out);
    k_norm<<<48, 256>>>(out);
}